// round 7
// baseline (speedup 1.0000x reference)
#include <cuda_runtime.h>

// SinkhornM: per-row MLP (8->32->16->9) -> tau -> sigmoid shares -> 10-iter
// Sinkhorn (u/v form) -> assemble 4x4 mus + V.
// Neuron-SIMD f32x2, two rows per thread.
// Port balancing: layer-2 weights (the largest, 2KB) are read from SHARED
// memory (broadcast LDS.128, crossbar nearly idle); layer-1/3 + biases stay
// in __constant__ (LDC). This halves constant-port pressure (LDC->LDC has an
// 8-cyc structural floor on sm_103a; it was ~60% busy and colliding with fma).

typedef unsigned long long F2;

// Constant block (layer-2 weights now live in shared, loaded from gPack).
#define OFF_W1 0
#define OFF_B1 256
#define OFF_W2 288
#define OFF_B2 800
#define OFF_W3 816
#define OFF_B3 1008
__constant__ float cAll[1024];
__device__ float gPack[1024];

__global__ void pack_weights_kernel(const float* __restrict__ W1, const float* __restrict__ b1,
                                    const float* __restrict__ W2, const float* __restrict__ b2,
                                    const float* __restrict__ W3, const float* __restrict__ b3)
{
    const int i = threadIdx.x;                 // 256 threads
    gPack[OFF_W1 + i] = W1[i];
    if (i < 32)  gPack[OFF_B1 + i] = b1[i];
    gPack[OFF_W2 + i]       = W2[i];
    gPack[OFF_W2 + 256 + i] = W2[256 + i];
    if (i < 16)  gPack[OFF_B2 + i] = b2[i];
    if (i < 192){
        int r = i / 12, c = i % 12;
        gPack[OFF_W3 + i] = (c < 9) ? W3[r * 9 + c] : 0.0f;
    }
    if (i < 12)  gPack[OFF_B3 + i] = (i < 9) ? b3[i] : 0.0f;
    if (i >= 252) gPack[768 + i] = 0.0f;       // pad [1020,1024)
}

static __device__ __forceinline__ float f2lo(F2 v){ return __uint_as_float((unsigned)v); }
static __device__ __forceinline__ float f2hi(F2 v){ return __uint_as_float((unsigned)(v >> 32)); }
static __device__ __forceinline__ F2 mkf2(float lo, float hi){
    return (F2)__float_as_uint(lo) | ((F2)__float_as_uint(hi) << 32);
}
static __device__ __forceinline__ F2 bb(float v){ return mkf2(v, v); }

static __device__ __forceinline__ F2 fma2(F2 a, F2 b, F2 c){
    F2 d; asm("fma.rn.f32x2 %0, %1, %2, %3;" : "=l"(d) : "l"(a), "l"(b), "l"(c)); return d;
}
static __device__ __forceinline__ F2 mul2(F2 a, F2 b){
    F2 d; asm("mul.rn.f32x2 %0, %1, %2;" : "=l"(d) : "l"(a), "l"(b)); return d;
}
static __device__ __forceinline__ F2 add2(F2 a, F2 b){
    F2 d; asm("add.rn.f32x2 %0, %1, %2;" : "=l"(d) : "l"(a), "l"(b)); return d;
}
static __device__ __forceinline__ float rcpa(float x){ float r; asm("rcp.approx.ftz.f32 %0, %1;" : "=f"(r) : "f"(x)); return r; }
static __device__ __forceinline__ float sqrta(float x){ float r; asm("sqrt.approx.ftz.f32 %0, %1;" : "=f"(r) : "f"(x)); return r; }
static __device__ __forceinline__ float ex2a(float x){ float r; asm("ex2.approx.ftz.f32 %0, %1;" : "=f"(r) : "f"(x)); return r; }

static __device__ __forceinline__ F2 rcp2(F2 v){ return mkf2(rcpa(f2lo(v)), rcpa(f2hi(v))); }
static __device__ __forceinline__ F2 sqrt2(F2 v){ return mkf2(sqrta(f2lo(v)), sqrta(f2hi(v))); }
static __device__ __forceinline__ F2 ex2_2(F2 v){ return mkf2(ex2a(f2lo(v)), ex2a(f2hi(v))); }
static __device__ __forceinline__ F2 dupf(float v){ return mkf2(v, v); }

__global__ __launch_bounds__(128, 6)
void sinkhornm_kernel(const float* __restrict__ margins,
                      float* __restrict__ out, int Btot, long long outsz)
{
    __shared__ __align__(16) float sW2s[512];   // layer-2 weights [32][16]

    const int tid = threadIdx.x;
    // Cooperative load of layer-2 weights BEFORE any early return.
    {
        const float4* src = (const float4*)(gPack + OFF_W2);
        float4* dst = (float4*)sW2s;
        dst[tid] = src[tid];                    // 128 threads x 16B = 2KB
    }
    __syncthreads();

    const long long t  = (long long)blockIdx.x * blockDim.x + tid;
    const long long r0 = 2 * t;
    if (r0 >= Btot) return;
    const bool hasHi = (r0 + 1) < Btot;
    const long long r1 = hasHi ? (r0 + 1) : r0;

    // Load margins for two rows; duplicate each scalar into (x,x) for the MLP.
    const float4* mga = (const float4*)(margins + r0 * 8);
    const float4* mgb = (const float4*)(margins + r1 * 8);
    const float4 a0 = mga[0], a1 = mga[1];
    const float4 q0 = mgb[0], q1 = mgb[1];

    F2 xA[8], xB[8];
    xA[0]=dupf(a0.x); xA[1]=dupf(a0.y); xA[2]=dupf(a0.z); xA[3]=dupf(a0.w);
    xA[4]=dupf(a1.x); xA[5]=dupf(a1.y); xA[6]=dupf(a1.z); xA[7]=dupf(a1.w);
    xB[0]=dupf(q0.x); xB[1]=dupf(q0.y); xB[2]=dupf(q0.z); xB[3]=dupf(q0.w);
    xB[4]=dupf(q1.x); xB[5]=dupf(q1.y); xB[6]=dupf(q1.z); xB[7]=dupf(q1.w);

    // ---- Fused layers 1+2 ----
    F2 gA[8], gB[8];
    {
        #pragma unroll
        for (int j = 0; j < 4; j++){
            float4 b = *(const float4*)(cAll + OFF_B2 + 4*j);
            F2 w01 = mkf2(b.x, b.y), w23 = mkf2(b.z, b.w);
            gA[2*j] = w01; gA[2*j+1] = w23;
            gB[2*j] = w01; gB[2*j+1] = w23;
        }
    }
    #pragma unroll
    for (int q = 0; q < 8; q++){
        float4 b = *(const float4*)(cAll + OFF_B1 + 4*q);
        F2 h0A = mkf2(b.x, b.y), h1A = mkf2(b.z, b.w);
        F2 h0B = h0A, h1B = h1A;
        #pragma unroll
        for (int k = 0; k < 8; k++){
            float4 w = *(const float4*)(cAll + OFF_W1 + (k*8 + q)*4);
            F2 w01 = mkf2(w.x, w.y), w23 = mkf2(w.z, w.w);
            h0A = fma2(xA[k], w01, h0A); h1A = fma2(xA[k], w23, h1A);
            h0B = fma2(xB[k], w01, h0B); h1B = fma2(xB[k], w23, h1B);
        }
        float hAs[4] = { fmaxf(f2lo(h0A), 0.f), fmaxf(f2hi(h0A), 0.f),
                         fmaxf(f2lo(h1A), 0.f), fmaxf(f2hi(h1A), 0.f) };
        float hBs[4] = { fmaxf(f2lo(h0B), 0.f), fmaxf(f2hi(h0B), 0.f),
                         fmaxf(f2lo(h1B), 0.f), fmaxf(f2hi(h1B), 0.f) };
        #pragma unroll
        for (int s = 0; s < 4; s++){
            const int k2 = 4*q + s;
            F2 ya = dupf(hAs[s]), yb = dupf(hBs[s]);
            #pragma unroll
            for (int j = 0; j < 4; j++){
                float4 w = *(const float4*)(sW2s + (k2*4 + j)*4);  // shared
                F2 w01 = mkf2(w.x, w.y), w23 = mkf2(w.z, w.w);
                gA[2*j]   = fma2(ya, w01, gA[2*j]);
                gA[2*j+1] = fma2(ya, w23, gA[2*j+1]);
                gB[2*j]   = fma2(yb, w01, gB[2*j]);
                gB[2*j+1] = fma2(yb, w23, gB[2*j+1]);
            }
        }
    }

    // Row-packed margins for later stages
    F2 mP[6];
    #pragma unroll
    for (int k = 0; k < 6; k++) mP[k] = mkf2(f2lo(xA[k]), f2lo(xB[k]));

    // ---- Layer 3: 16 -> 9 (padded to 10) ----
    F2 P0A, P1A, P2A, P3A, P4A, P0B, P1B, P2B, P3B, P4B;
    {
        float4 c0 = *(const float4*)(cAll + OFF_B3);
        float4 c1 = *(const float4*)(cAll + OFF_B3 + 4);
        F2 b8 = *(const F2*)(cAll + OFF_B3 + 8);
        P0A = mkf2(c0.x, c0.y); P1A = mkf2(c0.z, c0.w);
        P2A = mkf2(c1.x, c1.y); P3A = mkf2(c1.z, c1.w);
        P4A = b8;
        P0B = P0A; P1B = P1A; P2B = P2A; P3B = P3A; P4B = P4A;
    }
    #pragma unroll
    for (int k = 0; k < 16; k++){
        float va = fmaxf((k & 1) ? f2hi(gA[k >> 1]) : f2lo(gA[k >> 1]), 0.f);
        float vb = fmaxf((k & 1) ? f2hi(gB[k >> 1]) : f2lo(gB[k >> 1]), 0.f);
        F2 ya = dupf(va), yb = dupf(vb);
        float4 w0 = *(const float4*)(cAll + OFF_W3 + k*12);
        float4 w1 = *(const float4*)(cAll + OFF_W3 + k*12 + 4);
        F2 w8 = *(const F2*)(cAll + OFF_W3 + k*12 + 8);
        F2 w01 = mkf2(w0.x, w0.y), w23 = mkf2(w0.z, w0.w);
        F2 w45 = mkf2(w1.x, w1.y), w67 = mkf2(w1.z, w1.w);
        P0A = fma2(ya, w01, P0A); P1A = fma2(ya, w23, P1A);
        P2A = fma2(ya, w45, P2A); P3A = fma2(ya, w67, P3A);
        P4A = fma2(ya, w8,  P4A);
        P0B = fma2(yb, w01, P0B); P1B = fma2(yb, w23, P1B);
        P2B = fma2(yb, w45, P2B); P3B = fma2(yb, w67, P3B);
        P4B = fma2(yb, w8,  P4B);
    }

    // Repack p to row-SIMD
    F2 p0 = mkf2(f2lo(P0A), f2lo(P0B)), p1 = mkf2(f2hi(P0A), f2hi(P0B));
    F2 p2 = mkf2(f2lo(P1A), f2lo(P1B)), p3 = mkf2(f2hi(P1A), f2hi(P1B));
    F2 p4 = mkf2(f2lo(P2A), f2lo(P2B)), p5 = mkf2(f2hi(P2A), f2hi(P2B));
    F2 p6 = mkf2(f2lo(P3A), f2lo(P3B)), p7 = mkf2(f2hi(P3A), f2hi(P3B));
    F2 p8 = mkf2(f2lo(P4A), f2lo(P4B));

    // ---- tau via half-exponents ----
    const F2 HL2E = bb(0.72134752044448170f);
    F2 G0 = ex2_2(mul2(p0, HL2E));
    F2 G1 = ex2_2(mul2(p1, HL2E));
    F2 G2 = ex2_2(mul2(p2, HL2E));
    F2 G3 = ex2_2(mul2(p3, HL2E));
    F2 A0 = mul2(G0, G0), A1 = mul2(G1, G1), A2 = mul2(G0, G1);
    F2 A3 = mul2(G2, G2), A4 = mul2(G3, G3), A5 = mul2(G2, G3);
    F2 A6 = mul2(G0, G2), A7 = mul2(G1, G3);
    F2 A8 = sqrt2(mul2(A6, A7));

    // ---- sqs + V ----
    const F2 NL2E = bb(-1.4426950408889634f);
    const F2 L2E  = bb( 1.4426950408889634f);
    const F2 ONE  = bb(1.0f);
    const F2 C96  = bb(0.96f);
    const F2 C02  = bb(0.02f);
    F2 sm0 = fma2(rcp2(add2(ex2_2(mul2(p4, NL2E)), ONE)), C96, C02);
    F2 sm1 = fma2(rcp2(add2(ex2_2(mul2(p5, NL2E)), ONE)), C96, C02);
    F2 sf0 = fma2(rcp2(add2(ex2_2(mul2(p6, NL2E)), ONE)), C96, C02);
    F2 sf1 = fma2(rcp2(add2(ex2_2(mul2(p7, NL2E)), ONE)), C96, C02);
    F2 Vv  = ex2_2(mul2(p8, L2E));

    F2 rr0 = mul2(mP[0], sm0), rr1 = mul2(mP[1], sm1), rr2 = mP[2];
    F2 cc0 = mul2(mP[3], sf0), cc1 = mul2(mP[4], sf1), cc2 = mP[5];

    // ---- Sinkhorn, u/v form ----
    F2 u0, u1, u2, v0, v1, v2;
    {
        F2 t0 = add2(add2(A0, A1), A2); u0 = mul2(rr0, rcp2(t0));
        F2 t1 = add2(add2(A3, A4), A5); u1 = mul2(rr1, rcp2(t1));
        F2 t2 = add2(add2(A6, A7), A8); u2 = mul2(rr2, rcp2(t2));
        F2 s0 = fma2(A6, u2, fma2(A3, u1, mul2(A0, u0))); v0 = mul2(cc0, rcp2(s0));
        F2 s1 = fma2(A7, u2, fma2(A4, u1, mul2(A1, u0))); v1 = mul2(cc1, rcp2(s1));
        F2 s2 = fma2(A8, u2, fma2(A5, u1, mul2(A2, u0))); v2 = mul2(cc2, rcp2(s2));
    }
    #pragma unroll 1
    for (int it = 1; it < 10; it++){
        F2 t0 = fma2(A2, v2, fma2(A1, v1, mul2(A0, v0))); u0 = mul2(rr0, rcp2(t0));
        F2 t1 = fma2(A5, v2, fma2(A4, v1, mul2(A3, v0))); u1 = mul2(rr1, rcp2(t1));
        F2 t2 = fma2(A8, v2, fma2(A7, v1, mul2(A6, v0))); u2 = mul2(rr2, rcp2(t2));
        F2 s0 = fma2(A6, u2, fma2(A3, u1, mul2(A0, u0))); v0 = mul2(cc0, rcp2(s0));
        F2 s1 = fma2(A7, u2, fma2(A4, u1, mul2(A1, u0))); v1 = mul2(cc1, rcp2(s1));
        F2 s2 = fma2(A8, u2, fma2(A5, u1, mul2(A2, u0))); v2 = mul2(cc2, rcp2(s2));
    }

    A0 = mul2(mul2(A0, u0), v0); A1 = mul2(mul2(A1, u0), v1); A2 = mul2(mul2(A2, u0), v2);
    A3 = mul2(mul2(A3, u1), v0); A4 = mul2(mul2(A4, u1), v1); A5 = mul2(mul2(A5, u1), v2);
    A6 = mul2(mul2(A6, u2), v0); A7 = mul2(mul2(A7, u2), v1); A8 = mul2(mul2(A8, u2), v2);

    // ---- Assemble 4x4 mus + V ----
    {
        float m0 = f2lo(mP[0]) - f2lo(rr0);
        float m1 = f2lo(mP[1]) - f2lo(rr1);
        float f0 = f2lo(mP[3]) - f2lo(cc0);
        float f1 = f2lo(mP[4]) - f2lo(cc1);
        float4* o = (float4*)(out + r0 * 16);
        o[0] = make_float4(f2lo(A0), f2lo(A1), f2lo(A2), m0);
        o[1] = make_float4(f2lo(A3), f2lo(A4), f2lo(A5), m1);
        o[2] = make_float4(f2lo(A6), f2lo(A7), f2lo(A8), 0.f);
        o[3] = make_float4(f0, f1, 0.f, 0.f);
        long long vidx = (long long)Btot * 16 + r0;
        if (vidx < outsz) out[vidx] = f2lo(Vv);
    }
    if (hasHi){
        float m0 = f2hi(mP[0]) - f2hi(rr0);
        float m1 = f2hi(mP[1]) - f2hi(rr1);
        float f0 = f2hi(mP[3]) - f2hi(cc0);
        float f1 = f2hi(mP[4]) - f2hi(cc1);
        float4* o = (float4*)(out + r1 * 16);
        o[0] = make_float4(f2hi(A0), f2hi(A1), f2hi(A2), m0);
        o[1] = make_float4(f2hi(A3), f2hi(A4), f2hi(A5), m1);
        o[2] = make_float4(f2hi(A6), f2hi(A7), f2hi(A8), 0.f);
        o[3] = make_float4(f0, f1, 0.f, 0.f);
        long long vidx = (long long)Btot * 16 + r1;
        if (vidx < outsz) out[vidx] = f2hi(Vv);
    }
}

extern "C" void kernel_launch(void* const* d_in, const int* in_sizes, int n_in,
                              void* d_out, int out_size)
{
    const float* margins = (const float*)d_in[0];
    const float* W1 = (const float*)d_in[1];
    const float* b1 = (const float*)d_in[2];
    const float* W2 = (const float*)d_in[3];
    const float* b2 = (const float*)d_in[4];
    const float* W3 = (const float*)d_in[5];
    const float* b3 = (const float*)d_in[6];
    float* out = (float*)d_out;

    // Stage weights: one pack kernel + one 4KB D2D copy into constant memory.
    pack_weights_kernel<<<1, 256>>>(W1, b1, W2, b2, W3, b3);
    void* gPackDev = 0;
    cudaGetSymbolAddress(&gPackDev, gPack);
    cudaMemcpyToSymbolAsync(cAll, gPackDev, 1024 * sizeof(float), 0,
                            cudaMemcpyDeviceToDevice);

    const int B = in_sizes[0] / 8;
    const int nthreads = (B + 1) / 2;
    const int block = 128;
    const int grid = (nthreads + block - 1) / block;
    (void)n_in;
    sinkhornm_kernel<<<grid, block>>>(margins, out, B, (long long)out_size);
}

// round 8
// speedup vs baseline: 1.2065x; 1.2065x over previous
#include <cuda_runtime.h>

// SinkhornM: per-row MLP (8->32->16->9) -> tau -> sigmoid shares -> 10-iter
// Sinkhorn (u/v form) -> assemble 4x4 mus + V.
// Neuron-SIMD f32x2, two rows per thread; ALL weights in __constant__ (LDC).
// Round 7 (W2 in shared) regressed: L1 crossbar is the scarcer resource, the
// constant port pipelines fine. This round: revert to all-constant and raise
// occupancy to 7 CTAs/SM (regs 80 -> <=73).

typedef unsigned long long F2;

// Single constant block, fixed float4-aligned offsets.
#define OFF_W1 0
#define OFF_B1 256
#define OFF_W2 288
#define OFF_B2 800
#define OFF_W3 816
#define OFF_B3 1008
__constant__ float cAll[1024];
__device__ float gPack[1024];

__global__ void pack_weights_kernel(const float* __restrict__ W1, const float* __restrict__ b1,
                                    const float* __restrict__ W2, const float* __restrict__ b2,
                                    const float* __restrict__ W3, const float* __restrict__ b3)
{
    const int i = threadIdx.x;                 // 256 threads
    gPack[OFF_W1 + i] = W1[i];
    if (i < 32)  gPack[OFF_B1 + i] = b1[i];
    gPack[OFF_W2 + i]       = W2[i];
    gPack[OFF_W2 + 256 + i] = W2[256 + i];
    if (i < 16)  gPack[OFF_B2 + i] = b2[i];
    if (i < 192){
        int r = i / 12, c = i % 12;
        gPack[OFF_W3 + i] = (c < 9) ? W3[r * 9 + c] : 0.0f;
    }
    if (i < 12)  gPack[OFF_B3 + i] = (i < 9) ? b3[i] : 0.0f;
    if (i >= 252) gPack[768 + i] = 0.0f;       // pad [1020,1024)
}

static __device__ __forceinline__ float f2lo(F2 v){ return __uint_as_float((unsigned)v); }
static __device__ __forceinline__ float f2hi(F2 v){ return __uint_as_float((unsigned)(v >> 32)); }
static __device__ __forceinline__ F2 mkf2(float lo, float hi){
    return (F2)__float_as_uint(lo) | ((F2)__float_as_uint(hi) << 32);
}
static __device__ __forceinline__ F2 bb(float v){ return mkf2(v, v); }

static __device__ __forceinline__ F2 fma2(F2 a, F2 b, F2 c){
    F2 d; asm("fma.rn.f32x2 %0, %1, %2, %3;" : "=l"(d) : "l"(a), "l"(b), "l"(c)); return d;
}
static __device__ __forceinline__ F2 mul2(F2 a, F2 b){
    F2 d; asm("mul.rn.f32x2 %0, %1, %2;" : "=l"(d) : "l"(a), "l"(b)); return d;
}
static __device__ __forceinline__ F2 add2(F2 a, F2 b){
    F2 d; asm("add.rn.f32x2 %0, %1, %2;" : "=l"(d) : "l"(a), "l"(b)); return d;
}
static __device__ __forceinline__ float rcpa(float x){ float r; asm("rcp.approx.ftz.f32 %0, %1;" : "=f"(r) : "f"(x)); return r; }
static __device__ __forceinline__ float sqrta(float x){ float r; asm("sqrt.approx.ftz.f32 %0, %1;" : "=f"(r) : "f"(x)); return r; }
static __device__ __forceinline__ float ex2a(float x){ float r; asm("ex2.approx.ftz.f32 %0, %1;" : "=f"(r) : "f"(x)); return r; }

static __device__ __forceinline__ F2 rcp2(F2 v){ return mkf2(rcpa(f2lo(v)), rcpa(f2hi(v))); }
static __device__ __forceinline__ F2 sqrt2(F2 v){ return mkf2(sqrta(f2lo(v)), sqrta(f2hi(v))); }
static __device__ __forceinline__ F2 ex2_2(F2 v){ return mkf2(ex2a(f2lo(v)), ex2a(f2hi(v))); }
static __device__ __forceinline__ F2 dupf(float v){ return mkf2(v, v); }

__global__ __launch_bounds__(128, 7)
void sinkhornm_kernel(const float* __restrict__ margins,
                      float* __restrict__ out, int Btot, long long outsz)
{
    const int tid = threadIdx.x;
    const long long t  = (long long)blockIdx.x * blockDim.x + tid;
    const long long r0 = 2 * t;
    if (r0 >= Btot) return;
    const bool hasHi = (r0 + 1) < Btot;
    const long long r1 = hasHi ? (r0 + 1) : r0;

    // Load margins for two rows; duplicate each scalar into (x,x) for the MLP.
    const float4* mga = (const float4*)(margins + r0 * 8);
    const float4* mgb = (const float4*)(margins + r1 * 8);
    const float4 a0 = mga[0], a1 = mga[1];
    const float4 q0 = mgb[0], q1 = mgb[1];

    F2 xA[8], xB[8];
    xA[0]=dupf(a0.x); xA[1]=dupf(a0.y); xA[2]=dupf(a0.z); xA[3]=dupf(a0.w);
    xA[4]=dupf(a1.x); xA[5]=dupf(a1.y); xA[6]=dupf(a1.z); xA[7]=dupf(a1.w);
    xB[0]=dupf(q0.x); xB[1]=dupf(q0.y); xB[2]=dupf(q0.z); xB[3]=dupf(q0.w);
    xB[4]=dupf(q1.x); xB[5]=dupf(q1.y); xB[6]=dupf(q1.z); xB[7]=dupf(q1.w);

    // ---- Fused layers 1+2 ----
    F2 gA[8], gB[8];
    {
        #pragma unroll
        for (int j = 0; j < 4; j++){
            float4 b = *(const float4*)(cAll + OFF_B2 + 4*j);
            F2 w01 = mkf2(b.x, b.y), w23 = mkf2(b.z, b.w);
            gA[2*j] = w01; gA[2*j+1] = w23;
            gB[2*j] = w01; gB[2*j+1] = w23;
        }
    }
    #pragma unroll
    for (int q = 0; q < 8; q++){
        float4 b = *(const float4*)(cAll + OFF_B1 + 4*q);
        F2 h0A = mkf2(b.x, b.y), h1A = mkf2(b.z, b.w);
        F2 h0B = h0A, h1B = h1A;
        #pragma unroll
        for (int k = 0; k < 8; k++){
            float4 w = *(const float4*)(cAll + OFF_W1 + (k*8 + q)*4);
            F2 w01 = mkf2(w.x, w.y), w23 = mkf2(w.z, w.w);
            h0A = fma2(xA[k], w01, h0A); h1A = fma2(xA[k], w23, h1A);
            h0B = fma2(xB[k], w01, h0B); h1B = fma2(xB[k], w23, h1B);
        }
        float hAs[4] = { fmaxf(f2lo(h0A), 0.f), fmaxf(f2hi(h0A), 0.f),
                         fmaxf(f2lo(h1A), 0.f), fmaxf(f2hi(h1A), 0.f) };
        float hBs[4] = { fmaxf(f2lo(h0B), 0.f), fmaxf(f2hi(h0B), 0.f),
                         fmaxf(f2lo(h1B), 0.f), fmaxf(f2hi(h1B), 0.f) };
        #pragma unroll
        for (int s = 0; s < 4; s++){
            const int k2 = 4*q + s;
            F2 ya = dupf(hAs[s]), yb = dupf(hBs[s]);
            #pragma unroll
            for (int j = 0; j < 4; j++){
                float4 w = *(const float4*)(cAll + OFF_W2 + (k2*4 + j)*4);
                F2 w01 = mkf2(w.x, w.y), w23 = mkf2(w.z, w.w);
                gA[2*j]   = fma2(ya, w01, gA[2*j]);
                gA[2*j+1] = fma2(ya, w23, gA[2*j+1]);
                gB[2*j]   = fma2(yb, w01, gB[2*j]);
                gB[2*j+1] = fma2(yb, w23, gB[2*j+1]);
            }
        }
    }

    // Row-packed margins for later stages
    F2 mP[6];
    #pragma unroll
    for (int k = 0; k < 6; k++) mP[k] = mkf2(f2lo(xA[k]), f2lo(xB[k]));

    // ---- Layer 3: 16 -> 9 (padded to 10) ----
    F2 P0A, P1A, P2A, P3A, P4A, P0B, P1B, P2B, P3B, P4B;
    {
        float4 c0 = *(const float4*)(cAll + OFF_B3);
        float4 c1 = *(const float4*)(cAll + OFF_B3 + 4);
        F2 b8 = *(const F2*)(cAll + OFF_B3 + 8);
        P0A = mkf2(c0.x, c0.y); P1A = mkf2(c0.z, c0.w);
        P2A = mkf2(c1.x, c1.y); P3A = mkf2(c1.z, c1.w);
        P4A = b8;
        P0B = P0A; P1B = P1A; P2B = P2A; P3B = P3A; P4B = P4A;
    }
    #pragma unroll
    for (int k = 0; k < 16; k++){
        float va = fmaxf((k & 1) ? f2hi(gA[k >> 1]) : f2lo(gA[k >> 1]), 0.f);
        float vb = fmaxf((k & 1) ? f2hi(gB[k >> 1]) : f2lo(gB[k >> 1]), 0.f);
        F2 ya = dupf(va), yb = dupf(vb);
        float4 w0 = *(const float4*)(cAll + OFF_W3 + k*12);
        float4 w1 = *(const float4*)(cAll + OFF_W3 + k*12 + 4);
        F2 w8 = *(const F2*)(cAll + OFF_W3 + k*12 + 8);
        F2 w01 = mkf2(w0.x, w0.y), w23 = mkf2(w0.z, w0.w);
        F2 w45 = mkf2(w1.x, w1.y), w67 = mkf2(w1.z, w1.w);
        P0A = fma2(ya, w01, P0A); P1A = fma2(ya, w23, P1A);
        P2A = fma2(ya, w45, P2A); P3A = fma2(ya, w67, P3A);
        P4A = fma2(ya, w8,  P4A);
        P0B = fma2(yb, w01, P0B); P1B = fma2(yb, w23, P1B);
        P2B = fma2(yb, w45, P2B); P3B = fma2(yb, w67, P3B);
        P4B = fma2(yb, w8,  P4B);
    }

    // Repack p to row-SIMD
    F2 p0 = mkf2(f2lo(P0A), f2lo(P0B)), p1 = mkf2(f2hi(P0A), f2hi(P0B));
    F2 p2 = mkf2(f2lo(P1A), f2lo(P1B)), p3 = mkf2(f2hi(P1A), f2hi(P1B));
    F2 p4 = mkf2(f2lo(P2A), f2lo(P2B)), p5 = mkf2(f2hi(P2A), f2hi(P2B));
    F2 p6 = mkf2(f2lo(P3A), f2lo(P3B)), p7 = mkf2(f2hi(P3A), f2hi(P3B));
    F2 p8 = mkf2(f2lo(P4A), f2lo(P4B));

    // ---- tau via half-exponents ----
    const F2 HL2E = bb(0.72134752044448170f);
    F2 G0 = ex2_2(mul2(p0, HL2E));
    F2 G1 = ex2_2(mul2(p1, HL2E));
    F2 G2 = ex2_2(mul2(p2, HL2E));
    F2 G3 = ex2_2(mul2(p3, HL2E));
    F2 A0 = mul2(G0, G0), A1 = mul2(G1, G1), A2 = mul2(G0, G1);
    F2 A3 = mul2(G2, G2), A4 = mul2(G3, G3), A5 = mul2(G2, G3);
    F2 A6 = mul2(G0, G2), A7 = mul2(G1, G3);
    F2 A8 = sqrt2(mul2(A6, A7));

    // ---- sqs + V ----
    const F2 NL2E = bb(-1.4426950408889634f);
    const F2 L2E  = bb( 1.4426950408889634f);
    const F2 ONE  = bb(1.0f);
    const F2 C96  = bb(0.96f);
    const F2 C02  = bb(0.02f);
    F2 sm0 = fma2(rcp2(add2(ex2_2(mul2(p4, NL2E)), ONE)), C96, C02);
    F2 sm1 = fma2(rcp2(add2(ex2_2(mul2(p5, NL2E)), ONE)), C96, C02);
    F2 sf0 = fma2(rcp2(add2(ex2_2(mul2(p6, NL2E)), ONE)), C96, C02);
    F2 sf1 = fma2(rcp2(add2(ex2_2(mul2(p7, NL2E)), ONE)), C96, C02);
    F2 Vv  = ex2_2(mul2(p8, L2E));

    F2 rr0 = mul2(mP[0], sm0), rr1 = mul2(mP[1], sm1), rr2 = mP[2];
    F2 cc0 = mul2(mP[3], sf0), cc1 = mul2(mP[4], sf1), cc2 = mP[5];

    // ---- Sinkhorn, u/v form ----
    F2 u0, u1, u2, v0, v1, v2;
    {
        F2 t0 = add2(add2(A0, A1), A2); u0 = mul2(rr0, rcp2(t0));
        F2 t1 = add2(add2(A3, A4), A5); u1 = mul2(rr1, rcp2(t1));
        F2 t2 = add2(add2(A6, A7), A8); u2 = mul2(rr2, rcp2(t2));
        F2 s0 = fma2(A6, u2, fma2(A3, u1, mul2(A0, u0))); v0 = mul2(cc0, rcp2(s0));
        F2 s1 = fma2(A7, u2, fma2(A4, u1, mul2(A1, u0))); v1 = mul2(cc1, rcp2(s1));
        F2 s2 = fma2(A8, u2, fma2(A5, u1, mul2(A2, u0))); v2 = mul2(cc2, rcp2(s2));
    }
    #pragma unroll 1
    for (int it = 1; it < 10; it++){
        F2 t0 = fma2(A2, v2, fma2(A1, v1, mul2(A0, v0))); u0 = mul2(rr0, rcp2(t0));
        F2 t1 = fma2(A5, v2, fma2(A4, v1, mul2(A3, v0))); u1 = mul2(rr1, rcp2(t1));
        F2 t2 = fma2(A8, v2, fma2(A7, v1, mul2(A6, v0))); u2 = mul2(rr2, rcp2(t2));
        F2 s0 = fma2(A6, u2, fma2(A3, u1, mul2(A0, u0))); v0 = mul2(cc0, rcp2(s0));
        F2 s1 = fma2(A7, u2, fma2(A4, u1, mul2(A1, u0))); v1 = mul2(cc1, rcp2(s1));
        F2 s2 = fma2(A8, u2, fma2(A5, u1, mul2(A2, u0))); v2 = mul2(cc2, rcp2(s2));
    }

    A0 = mul2(mul2(A0, u0), v0); A1 = mul2(mul2(A1, u0), v1); A2 = mul2(mul2(A2, u0), v2);
    A3 = mul2(mul2(A3, u1), v0); A4 = mul2(mul2(A4, u1), v1); A5 = mul2(mul2(A5, u1), v2);
    A6 = mul2(mul2(A6, u2), v0); A7 = mul2(mul2(A7, u2), v1); A8 = mul2(mul2(A8, u2), v2);

    // ---- Assemble 4x4 mus + V ----
    {
        float m0 = f2lo(mP[0]) - f2lo(rr0);
        float m1 = f2lo(mP[1]) - f2lo(rr1);
        float f0 = f2lo(mP[3]) - f2lo(cc0);
        float f1 = f2lo(mP[4]) - f2lo(cc1);
        float4* o = (float4*)(out + r0 * 16);
        o[0] = make_float4(f2lo(A0), f2lo(A1), f2lo(A2), m0);
        o[1] = make_float4(f2lo(A3), f2lo(A4), f2lo(A5), m1);
        o[2] = make_float4(f2lo(A6), f2lo(A7), f2lo(A8), 0.f);
        o[3] = make_float4(f0, f1, 0.f, 0.f);
        long long vidx = (long long)Btot * 16 + r0;
        if (vidx < outsz) out[vidx] = f2lo(Vv);
    }
    if (hasHi){
        float m0 = f2hi(mP[0]) - f2hi(rr0);
        float m1 = f2hi(mP[1]) - f2hi(rr1);
        float f0 = f2hi(mP[3]) - f2hi(cc0);
        float f1 = f2hi(mP[4]) - f2hi(cc1);
        float4* o = (float4*)(out + r1 * 16);
        o[0] = make_float4(f2hi(A0), f2hi(A1), f2hi(A2), m0);
        o[1] = make_float4(f2hi(A3), f2hi(A4), f2hi(A5), m1);
        o[2] = make_float4(f2hi(A6), f2hi(A7), f2hi(A8), 0.f);
        o[3] = make_float4(f0, f1, 0.f, 0.f);
        long long vidx = (long long)Btot * 16 + r1;
        if (vidx < outsz) out[vidx] = f2hi(Vv);
    }
}

extern "C" void kernel_launch(void* const* d_in, const int* in_sizes, int n_in,
                              void* d_out, int out_size)
{
    const float* margins = (const float*)d_in[0];
    const float* W1 = (const float*)d_in[1];
    const float* b1 = (const float*)d_in[2];
    const float* W2 = (const float*)d_in[3];
    const float* b2 = (const float*)d_in[4];
    const float* W3 = (const float*)d_in[5];
    const float* b3 = (const float*)d_in[6];
    float* out = (float*)d_out;

    // Stage weights: one pack kernel + one 4KB D2D copy into constant memory.
    pack_weights_kernel<<<1, 256>>>(W1, b1, W2, b2, W3, b3);
    void* gPackDev = 0;
    cudaGetSymbolAddress(&gPackDev, gPack);
    cudaMemcpyToSymbolAsync(cAll, gPackDev, 1024 * sizeof(float), 0,
                            cudaMemcpyDeviceToDevice);

    const int B = in_sizes[0] / 8;
    const int nthreads = (B + 1) / 2;
    const int block = 128;
    const int grid = (nthreads + block - 1) / block;
    (void)n_in;
    sinkhornm_kernel<<<grid, block>>>(margins, out, B, (long long)out_size);
}